// round 1
// baseline (speedup 1.0000x reference)
#include <cuda_runtime.h>
#include <cuda_bf16.h>

#define DIM 128
#define MAX_NODES 100000

// Scratch for support = X @ W  (51.2 MB). Static device global per harness rules.
__device__ float g_support[MAX_NODES * DIM];

// ---------------------------------------------------------------------------
// Zero-init output (d_out is poisoned to 0xAA before timing).
// ---------------------------------------------------------------------------
__global__ void zero_out_kernel(float* __restrict__ out, int n_elems) {
    int idx = blockIdx.x * blockDim.x + threadIdx.x;
    int stride = gridDim.x * blockDim.x;
    int n4 = n_elems >> 2;
    float4 z = make_float4(0.f, 0.f, 0.f, 0.f);
    for (int i = idx; i < n4; i += stride)
        reinterpret_cast<float4*>(out)[i] = z;
}

// ---------------------------------------------------------------------------
// GEMM: S[n_rows, 128] = X[n_rows, 128] @ W[128, 128], fp32 SIMT.
// Block = 256 threads (8 warps), 64 rows per block, 8 rows per warp.
// W (64KB) + X tile (32KB) in dynamic smem.
// Per k-iter per warp: 1 LDS.128 (W) + 8 LDS.32 broadcasts (X) + 32 FFMA
//  -> smem crossbar ~8 cyc vs FFMA ~16 SMSP-cyc: FFMA-bound.
// ---------------------------------------------------------------------------
__global__ void __launch_bounds__(256) gemm_kernel(const float* __restrict__ X,
                                                   const float* __restrict__ W,
                                                   int n_rows) {
    extern __shared__ float sm[];
    float* Ws = sm;             // 128*128 floats
    float* Xs = sm + DIM * DIM; // 64*128 floats

    int tid = threadIdx.x;

    // Load full W into smem (coalesced float4).
    for (int i = tid * 4; i < DIM * DIM; i += blockDim.x * 4)
        *reinterpret_cast<float4*>(Ws + i) = *reinterpret_cast<const float4*>(W + i);

    // Load 64-row X tile into smem.
    int row0 = blockIdx.x * 64;
    for (int idx = tid; idx < 64 * (DIM / 4); idx += blockDim.x) {
        int r = idx >> 5;       // 0..63
        int c = idx & 31;       // float4 index 0..31
        int row = row0 + r;
        float4 v = make_float4(0.f, 0.f, 0.f, 0.f);
        if (row < n_rows)
            v = *reinterpret_cast<const float4*>(X + (long)row * DIM + c * 4);
        *reinterpret_cast<float4*>(Xs + r * DIM + c * 4) = v;
    }
    __syncthreads();

    int warp = tid >> 5;
    int lane = tid & 31;
    int rbase = warp * 8;

    float4 acc[8];
#pragma unroll
    for (int r = 0; r < 8; r++) acc[r] = make_float4(0.f, 0.f, 0.f, 0.f);

#pragma unroll 4
    for (int k = 0; k < DIM; k++) {
        float4 w = *reinterpret_cast<const float4*>(Ws + k * DIM + lane * 4);
#pragma unroll
        for (int r = 0; r < 8; r++) {
            float x = Xs[(rbase + r) * DIM + k];  // broadcast LDS
            acc[r].x += x * w.x;
            acc[r].y += x * w.y;
            acc[r].z += x * w.z;
            acc[r].w += x * w.w;
        }
    }

#pragma unroll
    for (int r = 0; r < 8; r++) {
        int row = row0 + rbase + r;
        if (row < n_rows)
            *reinterpret_cast<float4*>(g_support + (long)row * DIM + lane * 4) = acc[r];
    }
}

// ---------------------------------------------------------------------------
// Scatter: out[dst] += val * support[src] over 1.6M COO edges.
// One warp per edge: lane L handles float4 at column 4L. Edge metadata read
// broadcast (all lanes, same address -> 1 sector). Vector fp32 reduction
// (red.global.add.v4.f32, sm_90+) to quarter the atomic instruction count.
// ---------------------------------------------------------------------------
__device__ __forceinline__ void red_add_v4(float* addr, float4 v) {
    asm volatile("red.global.add.v4.f32 [%0], {%1, %2, %3, %4};"
                 :: "l"(addr), "f"(v.x), "f"(v.y), "f"(v.z), "f"(v.w)
                 : "memory");
}

__global__ void __launch_bounds__(256) scatter_kernel(const float* __restrict__ vals,
                                                      const int* __restrict__ src,
                                                      const int* __restrict__ dst,
                                                      float* __restrict__ out,
                                                      int n_edges) {
    int warp_global = (blockIdx.x * blockDim.x + threadIdx.x) >> 5;
    int lane = threadIdx.x & 31;
    int n_warps = (gridDim.x * blockDim.x) >> 5;

    for (int e = warp_global; e < n_edges; e += n_warps) {
        float v = __ldg(vals + e);
        int s = __ldg(src + e);
        int d = __ldg(dst + e);
        float4 sv = *reinterpret_cast<const float4*>(g_support + (long)s * DIM + lane * 4);
        float4 m = make_float4(sv.x * v, sv.y * v, sv.z * v, sv.w * v);
        red_add_v4(out + (long)d * DIM + lane * 4, m);
    }
}

// ---------------------------------------------------------------------------
// ReLU (neg_slope = 0): out = max(out, 0).
// ---------------------------------------------------------------------------
__global__ void relu_kernel(float* __restrict__ out, int n_elems) {
    int idx = blockIdx.x * blockDim.x + threadIdx.x;
    int stride = gridDim.x * blockDim.x;
    int n4 = n_elems >> 2;
    for (int i = idx; i < n4; i += stride) {
        float4 v = reinterpret_cast<float4*>(out)[i];
        v.x = fmaxf(v.x, 0.f);
        v.y = fmaxf(v.y, 0.f);
        v.z = fmaxf(v.z, 0.f);
        v.w = fmaxf(v.w, 0.f);
        reinterpret_cast<float4*>(out)[i] = v;
    }
}

extern "C" void kernel_launch(void* const* d_in, const int* in_sizes, int n_in,
                              void* d_out, int out_size) {
    const float* X    = (const float*)d_in[0];   // [n_nodes, 128]
    const float* W    = (const float*)d_in[1];   // [128, 128]
    const float* vals = (const float*)d_in[2];   // [E]
    const int*   src  = (const int*)d_in[3];     // [E]
    const int*   dst  = (const int*)d_in[4];     // [E]
    float* out = (float*)d_out;

    int n_nodes = in_sizes[0] / DIM;
    int n_edges = in_sizes[2];

    // 1. Zero output.
    zero_out_kernel<<<512, 256>>>(out, out_size);

    // 2. GEMM -> g_support. 96KB dynamic smem (W 64KB + X tile 32KB).
    const int smem_bytes = (DIM * DIM + 64 * DIM) * (int)sizeof(float);
    cudaFuncSetAttribute(gemm_kernel, cudaFuncAttributeMaxDynamicSharedMemorySize,
                         smem_bytes);
    int gemm_blocks = (n_nodes + 63) / 64;
    gemm_kernel<<<gemm_blocks, 256, smem_bytes>>>(X, W, n_nodes);

    // 3. Edge scatter with vector atomics. 1184 blocks * 8 warps = 9472 warps
    //    (64 warps/SM residency) to hide chained L2 latency.
    scatter_kernel<<<1184, 256>>>(vals, src, dst, out, n_edges);

    // 4. ReLU.
    relu_kernel<<<512, 256>>>(out, out_size);
}

// round 2
// speedup vs baseline: 1.0251x; 1.0251x over previous
#include <cuda_runtime.h>
#include <cuda_bf16.h>

#define DIM 128
#define MAX_NODES 100000
#define RPB 64   // GEMM rows per block

// Scratch for support = X @ W  (51.2 MB).
__device__ float g_support[MAX_NODES * DIM];

// ---------------------------------------------------------------------------
// f32x2 packed-FMA helpers (FFMA2 — only reachable via PTX fma.rn.f32x2)
// ---------------------------------------------------------------------------
__device__ __forceinline__ unsigned long long splat2(float x) {
    unsigned long long r;
    unsigned int xi = __float_as_uint(x);
    asm("mov.b64 %0, {%1, %1};" : "=l"(r) : "r"(xi));
    return r;
}
__device__ __forceinline__ void fma2(unsigned long long& d,
                                     unsigned long long a,
                                     unsigned long long b) {
    asm("fma.rn.f32x2 %0, %1, %2, %0;" : "+l"(d) : "l"(a), "l"(b));
}
__device__ __forceinline__ void unpack2(unsigned long long v, float& lo, float& hi) {
    unsigned int a, b;
    asm("mov.b64 {%0, %1}, %2;" : "=r"(a), "=r"(b) : "l"(v));
    lo = __uint_as_float(a);
    hi = __uint_as_float(b);
}

// ---------------------------------------------------------------------------
// Zero-init output (d_out poisoned to 0xAA before timing).
// ---------------------------------------------------------------------------
__global__ void zero_out_kernel(float* __restrict__ out, int n_elems) {
    int idx = blockIdx.x * blockDim.x + threadIdx.x;
    int stride = gridDim.x * blockDim.x;
    int n4 = n_elems >> 2;
    float4 z = make_float4(0.f, 0.f, 0.f, 0.f);
    for (int i = idx; i < n4; i += stride)
        reinterpret_cast<float4*>(out)[i] = z;
}

// ---------------------------------------------------------------------------
// GEMM: S = X @ W with packed f32x2 FMAs.
// Block 256 thr (8 warps), 64 rows/block. Warp tile: 8 rows x 128 cols.
// Xt = X tile TRANSPOSED in smem ([k][row], swizzled) so row-pairs are
// natural f32x2 operands (one LDS.128 = 4 rows). W float4 already pairs
// along cols. Per k per warp: 1 LDS.128(W) + 2 LDS.128(X) + 4 splats +
// 16 FFMA2 (= 32 FMAs/lane-pair). FFMA2-pipe bound.
// Swizzle uses bits[2:4] only: 4-row groups stay intact & ordered; the
// one-time transpose stores drop from 32-way to 4-way bank conflicts.
// ---------------------------------------------------------------------------
__global__ void __launch_bounds__(256) gemm_kernel(const float* __restrict__ X,
                                                   const float* __restrict__ W,
                                                   int n_rows) {
    extern __shared__ float sm[];
    float* Ws = sm;                // [128][128]  64KB
    float* Xt = sm + DIM * DIM;    // [128][64] transposed+swizzled  32KB

    int tid = threadIdx.x;

    // Load full W (coalesced float4).
    for (int i = tid * 4; i < DIM * DIM; i += 256 * 4)
        *reinterpret_cast<float4*>(Ws + i) = *reinterpret_cast<const float4*>(W + i);

    // Load X tile, transpose into Xt with swizzle.
    int row0 = blockIdx.x * RPB;
    for (int idx = tid; idx < RPB * 32; idx += 256) {
        int r = idx >> 5;        // 0..63
        int c4 = idx & 31;       // float4 index along k
        int row = row0 + r;
        float4 v = make_float4(0.f, 0.f, 0.f, 0.f);
        if (row < n_rows)
            v = *reinterpret_cast<const float4*>(X + (size_t)row * DIM + c4 * 4);
        int kb = c4 * 4;
        const float* vp = reinterpret_cast<const float*>(&v);
#pragma unroll
        for (int j = 0; j < 4; j++) {
            int k = kb + j;
            int rs = r ^ (((k >> 2) & 7) << 2);
            Xt[k * RPB + rs] = vp[j];
        }
    }
    __syncthreads();

    int warp = tid >> 5;
    int lane = tid & 31;
    int rbase = warp * 8;  // 8 rows per warp

    unsigned long long acc[4][4];  // [row-pair][col]
#pragma unroll
    for (int p = 0; p < 4; p++)
#pragma unroll
        for (int c = 0; c < 4; c++) acc[p][c] = 0ull;

#pragma unroll 8
    for (int k = 0; k < DIM; k++) {
        float4 w = *reinterpret_cast<const float4*>(Ws + k * DIM + lane * 4);
        unsigned long long w0 = splat2(w.x), w1 = splat2(w.y),
                           w2 = splat2(w.z), w3 = splat2(w.w);
        int swz = ((k >> 2) & 7) << 2;
        const float* xrow = Xt + k * RPB;
        ulonglong2 xa = *reinterpret_cast<const ulonglong2*>(xrow + (rbase ^ swz));
        ulonglong2 xb = *reinterpret_cast<const ulonglong2*>(xrow + ((rbase + 4) ^ swz));

        fma2(acc[0][0], xa.x, w0); fma2(acc[0][1], xa.x, w1);
        fma2(acc[0][2], xa.x, w2); fma2(acc[0][3], xa.x, w3);
        fma2(acc[1][0], xa.y, w0); fma2(acc[1][1], xa.y, w1);
        fma2(acc[1][2], xa.y, w2); fma2(acc[1][3], xa.y, w3);
        fma2(acc[2][0], xb.x, w0); fma2(acc[2][1], xb.x, w1);
        fma2(acc[2][2], xb.x, w2); fma2(acc[2][3], xb.x, w3);
        fma2(acc[3][0], xb.y, w0); fma2(acc[3][1], xb.y, w1);
        fma2(acc[3][2], xb.y, w2); fma2(acc[3][3], xb.y, w3);
    }

#pragma unroll
    for (int p = 0; p < 4; p++) {
        float lo[4], hi[4];
#pragma unroll
        for (int c = 0; c < 4; c++) unpack2(acc[p][c], lo[c], hi[c]);
        int r0 = row0 + rbase + 2 * p;
        if (r0 < n_rows)
            *reinterpret_cast<float4*>(g_support + (size_t)r0 * DIM + lane * 4) =
                make_float4(lo[0], lo[1], lo[2], lo[3]);
        if (r0 + 1 < n_rows)
            *reinterpret_cast<float4*>(g_support + (size_t)(r0 + 1) * DIM + lane * 4) =
                make_float4(hi[0], hi[1], hi[2], hi[3]);
    }
}

// ---------------------------------------------------------------------------
// Scatter: out[dst] += val * support[src] via red.global.add.v4.f32.
// One warp per edge; lane L owns float4 at col 4L. L2-BW bound (~1KB/edge).
// ---------------------------------------------------------------------------
__device__ __forceinline__ void red_add_v4(float* addr, float4 v) {
    asm volatile("red.global.add.v4.f32 [%0], {%1, %2, %3, %4};"
                 :: "l"(addr), "f"(v.x), "f"(v.y), "f"(v.z), "f"(v.w)
                 : "memory");
}

__global__ void __launch_bounds__(256) scatter_kernel(const float* __restrict__ vals,
                                                      const int* __restrict__ src,
                                                      const int* __restrict__ dst,
                                                      float* __restrict__ out,
                                                      int n_edges) {
    int warp_global = (blockIdx.x * blockDim.x + threadIdx.x) >> 5;
    int lane = threadIdx.x & 31;
    int n_warps = (gridDim.x * blockDim.x) >> 5;

    for (int e = warp_global; e < n_edges; e += n_warps) {
        float v = __ldg(vals + e);
        int s = __ldg(src + e);
        int d = __ldg(dst + e);
        float4 sv = *reinterpret_cast<const float4*>(g_support + (size_t)s * DIM + lane * 4);
        float4 m = make_float4(sv.x * v, sv.y * v, sv.z * v, sv.w * v);
        red_add_v4(out + (size_t)d * DIM + lane * 4, m);
    }
}

// ---------------------------------------------------------------------------
// ReLU (neg_slope = 0).
// ---------------------------------------------------------------------------
__global__ void relu_kernel(float* __restrict__ out, int n_elems) {
    int idx = blockIdx.x * blockDim.x + threadIdx.x;
    int stride = gridDim.x * blockDim.x;
    int n4 = n_elems >> 2;
    for (int i = idx; i < n4; i += stride) {
        float4 v = reinterpret_cast<float4*>(out)[i];
        v.x = fmaxf(v.x, 0.f);
        v.y = fmaxf(v.y, 0.f);
        v.z = fmaxf(v.z, 0.f);
        v.w = fmaxf(v.w, 0.f);
        reinterpret_cast<float4*>(out)[i] = v;
    }
}

extern "C" void kernel_launch(void* const* d_in, const int* in_sizes, int n_in,
                              void* d_out, int out_size) {
    const float* X    = (const float*)d_in[0];   // [n_nodes, 128]
    const float* W    = (const float*)d_in[1];   // [128, 128]
    const float* vals = (const float*)d_in[2];   // [E]
    const int*   src  = (const int*)d_in[3];     // [E]
    const int*   dst  = (const int*)d_in[4];     // [E]
    float* out = (float*)d_out;

    int n_nodes = in_sizes[0] / DIM;
    int n_edges = in_sizes[2];

    // 1. Zero output.
    zero_out_kernel<<<2048, 256>>>(out, out_size);

    // 2. GEMM -> g_support. 96KB dynamic smem (W 64KB + Xt 32KB) => 2 blocks/SM.
    const int smem_bytes = (DIM * DIM + RPB * DIM) * (int)sizeof(float);
    cudaFuncSetAttribute(gemm_kernel, cudaFuncAttributeMaxDynamicSharedMemorySize,
                         smem_bytes);
    int gemm_blocks = (n_nodes + RPB - 1) / RPB;
    gemm_kernel<<<gemm_blocks, 256, smem_bytes>>>(X, W, n_nodes);

    // 3. Edge scatter (L2-BW bound).
    scatter_kernel<<<1184, 256>>>(vals, src, dst, out, n_edges);

    // 4. ReLU.
    relu_kernel<<<2048, 256>>>(out, out_size);
}

// round 4
// speedup vs baseline: 1.6022x; 1.5630x over previous
#include <cuda_runtime.h>
#include <cuda_fp16.h>
#include <cstring>

#define DIM 128
#define MAX_NODES 100000
#define MAX_EDGES 1600000
#define RPB 64                    // GEMM rows per block
#define SCAN_BLK 1024             // elements per scan1 block
#define MAX_SCAN_BLOCKS 128       // supports up to 131072 nodes

// Static device scratch (no allocs allowed).
__device__ __half g_support[MAX_NODES * DIM];           // 25.6 MB, L2-resident
__device__ int g_count[MAX_NODES];
__device__ int g_offset[MAX_NODES];
__device__ int g_cursor[MAX_NODES];
__device__ int g_blocksums[MAX_SCAN_BLOCKS];
__device__ unsigned long long g_bins[MAX_EDGES];        // (val<<32)|src, 12.8 MB

// ---------------------------------------------------------------------------
// f32x2 packed-FMA helpers (FFMA2)
// ---------------------------------------------------------------------------
__device__ __forceinline__ unsigned long long splat2(float x) {
    unsigned long long r;
    unsigned int xi = __float_as_uint(x);
    asm("mov.b64 %0, {%1, %1};" : "=l"(r) : "r"(xi));
    return r;
}
__device__ __forceinline__ void fma2(unsigned long long& d,
                                     unsigned long long a,
                                     unsigned long long b) {
    asm("fma.rn.f32x2 %0, %1, %2, %0;" : "+l"(d) : "l"(a), "l"(b));
}
__device__ __forceinline__ void unpack2(unsigned long long v, float& lo, float& hi) {
    unsigned int a, b;
    asm("mov.b64 {%0, %1}, %2;" : "=r"(a), "=r"(b) : "l"(v));
    lo = __uint_as_float(a);
    hi = __uint_as_float(b);
}

__device__ __forceinline__ unsigned int pack_half2(float a, float b) {
    __half2 h = __floats2half2_rn(a, b);
    unsigned int u;
    memcpy(&u, &h, 4);
    return u;
}

// ---------------------------------------------------------------------------
// GEMM: support = X @ W (fp32 math, fp16 store). FFMA2 core.
// ---------------------------------------------------------------------------
__global__ void __launch_bounds__(256) gemm_kernel(const float* __restrict__ X,
                                                   const float* __restrict__ W,
                                                   int n_rows) {
    extern __shared__ float sm[];
    float* Ws = sm;                // [128][128]  64KB
    float* Xt = sm + DIM * DIM;    // [128][64] transposed+swizzled  32KB

    int tid = threadIdx.x;

    for (int i = tid * 4; i < DIM * DIM; i += 256 * 4)
        *reinterpret_cast<float4*>(Ws + i) = *reinterpret_cast<const float4*>(W + i);

    int row0 = blockIdx.x * RPB;
    for (int idx = tid; idx < RPB * 32; idx += 256) {
        int r = idx >> 5;
        int c4 = idx & 31;
        int row = row0 + r;
        float4 v = make_float4(0.f, 0.f, 0.f, 0.f);
        if (row < n_rows)
            v = *reinterpret_cast<const float4*>(X + (size_t)row * DIM + c4 * 4);
        int kb = c4 * 4;
        const float* vp = reinterpret_cast<const float*>(&v);
#pragma unroll
        for (int j = 0; j < 4; j++) {
            int k = kb + j;
            int rs = r ^ (((k >> 2) & 7) << 2);
            Xt[k * RPB + rs] = vp[j];
        }
    }
    __syncthreads();

    int warp = tid >> 5;
    int lane = tid & 31;
    int rbase = warp * 8;

    unsigned long long acc[4][4];
#pragma unroll
    for (int p = 0; p < 4; p++)
#pragma unroll
        for (int c = 0; c < 4; c++) acc[p][c] = 0ull;

#pragma unroll 8
    for (int k = 0; k < DIM; k++) {
        float4 w = *reinterpret_cast<const float4*>(Ws + k * DIM + lane * 4);
        unsigned long long w0 = splat2(w.x), w1 = splat2(w.y),
                           w2 = splat2(w.z), w3 = splat2(w.w);
        int swz = ((k >> 2) & 7) << 2;
        const float* xrow = Xt + k * RPB;
        ulonglong2 xa = *reinterpret_cast<const ulonglong2*>(xrow + (rbase ^ swz));
        ulonglong2 xb = *reinterpret_cast<const ulonglong2*>(xrow + ((rbase + 4) ^ swz));

        fma2(acc[0][0], xa.x, w0); fma2(acc[0][1], xa.x, w1);
        fma2(acc[0][2], xa.x, w2); fma2(acc[0][3], xa.x, w3);
        fma2(acc[1][0], xa.y, w0); fma2(acc[1][1], xa.y, w1);
        fma2(acc[1][2], xa.y, w2); fma2(acc[1][3], xa.y, w3);
        fma2(acc[2][0], xb.x, w0); fma2(acc[2][1], xb.x, w1);
        fma2(acc[2][2], xb.x, w2); fma2(acc[2][3], xb.x, w3);
        fma2(acc[3][0], xb.y, w0); fma2(acc[3][1], xb.y, w1);
        fma2(acc[3][2], xb.y, w2); fma2(acc[3][3], xb.y, w3);
    }

#pragma unroll
    for (int p = 0; p < 4; p++) {
        float lo[4], hi[4];
#pragma unroll
        for (int c = 0; c < 4; c++) unpack2(acc[p][c], lo[c], hi[c]);
        int r0 = row0 + rbase + 2 * p;
        if (r0 < n_rows) {
            uint2 st = make_uint2(pack_half2(lo[0], lo[1]), pack_half2(lo[2], lo[3]));
            *reinterpret_cast<uint2*>(g_support + (size_t)r0 * DIM + lane * 4) = st;
        }
        if (r0 + 1 < n_rows) {
            uint2 st = make_uint2(pack_half2(hi[0], hi[1]), pack_half2(hi[2], hi[3]));
            *reinterpret_cast<uint2*>(g_support + (size_t)(r0 + 1) * DIM + lane * 4) = st;
        }
    }
}

// ---------------------------------------------------------------------------
// CSR binning: zero counts -> histogram -> 3-phase exclusive scan -> fill.
// ---------------------------------------------------------------------------
__global__ void zero_counts_kernel(int n_nodes) {
    int i = blockIdx.x * blockDim.x + threadIdx.x;
    if (i < n_nodes) g_count[i] = 0;
}

__global__ void hist_kernel(const int* __restrict__ dst, int n_edges) {
    int i = blockIdx.x * blockDim.x + threadIdx.x;
    int stride = gridDim.x * blockDim.x;
    for (; i < n_edges; i += stride)
        atomicAdd(&g_count[dst[i]], 1);
}

// scan1: per-block (1024 elems) exclusive scan into g_offset + block sums.
__global__ void __launch_bounds__(256) scan1_kernel(int n_nodes) {
    __shared__ int s[256];
    int base = blockIdx.x * SCAN_BLK;
    int t = threadIdx.x;
    int v[4];
    int sum = 0;
#pragma unroll
    for (int j = 0; j < 4; j++) {
        int idx = base + t * 4 + j;
        v[j] = (idx < n_nodes) ? g_count[idx] : 0;
        sum += v[j];
    }
    s[t] = sum;
    __syncthreads();
    for (int off = 1; off < 256; off <<= 1) {
        int x = (t >= off) ? s[t - off] : 0;
        __syncthreads();
        s[t] += x;
        __syncthreads();
    }
    int excl = s[t] - sum;
    if (t == 255) g_blocksums[blockIdx.x] = s[255];
    int run = excl;
#pragma unroll
    for (int j = 0; j < 4; j++) {
        int idx = base + t * 4 + j;
        if (idx < n_nodes) g_offset[idx] = run;
        run += v[j];
    }
}

// scan2: single block exclusive scan of block sums (nb <= 128).
__global__ void __launch_bounds__(128) scan2_kernel(int nb) {
    __shared__ int s[128];
    int t = threadIdx.x;
    int v = (t < nb) ? g_blocksums[t] : 0;
    s[t] = v;
    __syncthreads();
    for (int off = 1; off < 128; off <<= 1) {
        int x = (t >= off) ? s[t - off] : 0;
        __syncthreads();
        s[t] += x;
        __syncthreads();
    }
    if (t < nb) g_blocksums[t] = s[t] - v;
}

// scan3: add block offsets, init cursors.
__global__ void scan3_kernel(int n_nodes) {
    int i = blockIdx.x * blockDim.x + threadIdx.x;
    if (i < n_nodes) {
        int o = g_offset[i] + g_blocksums[i / SCAN_BLK];
        g_offset[i] = o;
        g_cursor[i] = o;
    }
}

__global__ void fill_kernel(const float* __restrict__ vals,
                            const int* __restrict__ src,
                            const int* __restrict__ dst,
                            int n_edges) {
    int i = blockIdx.x * blockDim.x + threadIdx.x;
    if (i < n_edges) {
        int d = dst[i];
        int pos = atomicAdd(&g_cursor[d], 1);
        g_bins[pos] = ((unsigned long long)__float_as_uint(vals[i]) << 32) |
                      (unsigned int)src[i];
    }
}

// ---------------------------------------------------------------------------
// Gather: one warp per dst node. Lane L owns cols [4L,4L+4). 4-edge software
// pipeline for MLP. Fused ReLU + single output write per node.
// ---------------------------------------------------------------------------
__global__ void __launch_bounds__(256) gather_kernel(float* __restrict__ out,
                                                     int n_nodes) {
    int warp = (blockIdx.x * blockDim.x + threadIdx.x) >> 5;
    int lane = threadIdx.x & 31;
    if (warp >= n_nodes) return;

    int o0 = g_offset[warp];
    int deg = g_count[warp];

    float4 acc = make_float4(0.f, 0.f, 0.f, 0.f);

    for (int e = 0; e < deg; e += 4) {
        unsigned long long p[4];
#pragma unroll
        for (int j = 0; j < 4; j++)
            p[j] = (e + j < deg) ? __ldg(g_bins + o0 + e + j) : 0ull;  // val=0,src=0

        uint2 hv[4];
#pragma unroll
        for (int j = 0; j < 4; j++) {
            int s = (int)(p[j] & 0xffffffffull);
            hv[j] = __ldg(reinterpret_cast<const uint2*>(
                g_support + (size_t)s * DIM + lane * 4));
        }
#pragma unroll
        for (int j = 0; j < 4; j++) {
            float v = __uint_as_float((unsigned int)(p[j] >> 32));
            __half2 a, b;
            memcpy(&a, &hv[j].x, 4);
            memcpy(&b, &hv[j].y, 4);
            float2 fa = __half22float2(a);
            float2 fb = __half22float2(b);
            acc.x = fmaf(v, fa.x, acc.x);
            acc.y = fmaf(v, fa.y, acc.y);
            acc.z = fmaf(v, fb.x, acc.z);
            acc.w = fmaf(v, fb.y, acc.w);
        }
    }

    acc.x = fmaxf(acc.x, 0.f);
    acc.y = fmaxf(acc.y, 0.f);
    acc.z = fmaxf(acc.z, 0.f);
    acc.w = fmaxf(acc.w, 0.f);
    *reinterpret_cast<float4*>(out + (size_t)warp * DIM + lane * 4) = acc;
}

extern "C" void kernel_launch(void* const* d_in, const int* in_sizes, int n_in,
                              void* d_out, int out_size) {
    const float* X    = (const float*)d_in[0];   // [n_nodes, 128]
    const float* W    = (const float*)d_in[1];   // [128, 128]
    const float* vals = (const float*)d_in[2];   // [E]
    const int*   src  = (const int*)d_in[3];     // [E]
    const int*   dst  = (const int*)d_in[4];     // [E]
    float* out = (float*)d_out;

    int n_nodes = in_sizes[0] / DIM;
    int n_edges = in_sizes[2];
    int nb = (n_nodes + SCAN_BLK - 1) / SCAN_BLK;  // scan blocks (98 for 100K)

    // Binning pipeline (independent of GEMM).
    zero_counts_kernel<<<(n_nodes + 255) / 256, 256>>>(n_nodes);
    hist_kernel<<<2048, 256>>>(dst, n_edges);

    // GEMM -> g_support (fp16). 96KB dynamic smem.
    const int smem_bytes = (DIM * DIM + RPB * DIM) * (int)sizeof(float);
    cudaFuncSetAttribute(gemm_kernel, cudaFuncAttributeMaxDynamicSharedMemorySize,
                         smem_bytes);
    gemm_kernel<<<(n_nodes + RPB - 1) / RPB, 256, smem_bytes>>>(X, W, n_nodes);

    scan1_kernel<<<nb, 256>>>(n_nodes);
    scan2_kernel<<<1, 128>>>(nb);
    scan3_kernel<<<(n_nodes + 255) / 256, 256>>>(n_nodes);
    fill_kernel<<<(n_edges + 255) / 256, 256>>>(vals, src, dst, n_edges);

    // Gather + ReLU (one warp per node, writes every output exactly once).
    int blocks = (n_nodes * 32 + 255) / 256;
    gather_kernel<<<blocks, 256>>>(out, n_nodes);
}